// round 6
// baseline (speedup 1.0000x reference)
#include <cuda_runtime.h>
#include <math.h>

#define CH 24          // b*c independent planes
#define HI 192
#define WI 192
#define NI 186         // interior rows/cols
#define NBLK 6         // CTAs per plane = cluster size
#define WARPS 8
#define THREADS (WARPS*32)

typedef unsigned long long ull;

__device__ double   g_sumsq;
__device__ unsigned g_done;

__device__ __forceinline__ int ldAcqS(unsigned a) {
    int v;
    asm volatile("ld.acquire.cta.shared.b32 %0, [%1];" : "=r"(v) : "r"(a) : "memory");
    return v;
}
__device__ __forceinline__ int ldAcqClu(unsigned a) {
    int v;
    asm volatile("ld.acquire.cluster.shared::cta.b32 %0, [%1];" : "=r"(v) : "r"(a) : "memory");
    return v;
}
__device__ __forceinline__ void stRelS(unsigned a, int v) {
    asm volatile("st.release.cta.shared.b32 [%0], %1;" :: "r"(a), "r"(v) : "memory");
}
__device__ __forceinline__ unsigned mapaClu(unsigned a, unsigned rank) {
    unsigned r;
    asm("mapa.shared::cluster.u32 %0, %1, %2;" : "=r"(r) : "r"(a), "r"(rank));
    return r;
}
__device__ __forceinline__ void stRemoteF(unsigned a, float v) {
    asm volatile("st.shared::cluster.f32 [%0], %1;" :: "r"(a), "f"(v) : "memory");
}
__device__ __forceinline__ void stRelClu(unsigned a, int v) {
    asm volatile("st.release.cluster.shared::cluster.b32 [%0], %1;" :: "r"(a), "r"(v) : "memory");
}
__device__ __forceinline__ void fma2(ull& d, ull a, ull b) {
    asm("fma.rn.f32x2 %0, %1, %2, %0;" : "+l"(d) : "l"(a), "l"(b));
}
__device__ __forceinline__ float hsum2(ull v) {
    float lo, hi;
    asm("mov.b64 {%0, %1}, %2;" : "=f"(lo), "=f"(hi) : "l"(v));
    return lo + hi;
}
__device__ __forceinline__ ull packf2(float lo, float hi) {
    ull r;
    asm("mov.b64 %0, {%1, %2};" : "=l"(r) : "f"(lo), "f"(hi));
    return r;
}
// tanh(x) = 1 - 2/(e^{2x}+1), via ex2.approx + rcp.approx; abs err ~1e-6
__device__ __forceinline__ float ftanh(float x) {
    float e = __expf(2.0f * x);
    float r;
    asm("rcp.approx.f32 %0, %1;" : "=f"(r) : "f"(e + 1.0f));
    return fmaf(-2.0f, r, 1.0f);
}

__global__ void zero_kernel() {
    g_sumsq = 0.0;
    g_done  = 0;
}

__global__ __launch_bounds__(THREADS, 1) __cluster_dims__(NBLK, 1, 1)
void codec_kernel(const float* __restrict__ x,
                  const float* __restrict__ W1, const float* __restrict__ B1,
                  const float* __restrict__ W2, const float* __restrict__ B2,
                  const float* __restrict__ W3, const float* __restrict__ B3,
                  const float* __restrict__ W4, const float* __restrict__ B4,
                  float* __restrict__ out)
{
    // layer2/3 weights: k-major interleaved, element [k4*M + m] = float4(W[4k4+0..3][m])
    __shared__ __align__(16) ulonglong2 sW2q[24 * 24];
    __shared__ __align__(16) ulonglong2 sW3q[6 * 12];
    __shared__ float sB1[96], sB2[24], sB3[12], sW4[12];
    __shared__ float sB4v;
    __shared__ __align__(16) float sFeat[WARPS][48];
    __shared__ __align__(16) float sH1[WARPS][96];
    __shared__ __align__(16) float sH2[WARPS][24];
    __shared__ __align__(16) float sRing[WARPS][WI];   // own-CTA rows (cols 0..2 stay 0)
    __shared__ __align__(16) float sPrev[3][WI];       // rows i-3..i-1 pushed by prev cluster CTA
    __shared__ int sProg[WARPS];
    __shared__ int sPrevFlag;

    const int tid = threadIdx.x;

    {
        float* f2 = (float*)sW2q;
        for (int idx = tid; idx < 96 * 24; idx += THREADS) {
            int k = idx / 24, m = idx % 24;
            f2[((k >> 2) * 24 + m) * 4 + (k & 3)] = W2[idx];
        }
        float* f3 = (float*)sW3q;
        for (int idx = tid; idx < 24 * 12; idx += THREADS) {
            int k = idx / 12, m = idx % 12;
            f3[((k >> 2) * 12 + m) * 4 + (k & 3)] = W3[idx];
        }
    }
    if (tid < 96) sB1[tid] = B1[tid];
    if (tid < 24) sB2[tid] = B2[tid];
    if (tid < 12) sB3[tid] = B3[tid];
    if (tid < 12) sW4[tid] = W4[tid];
    if (tid == 0) { sB4v = B4[0]; sPrevFlag = 0; }
    for (int idx = tid; idx < WARPS * WI; idx += THREADS) ((float*)sRing)[idx] = 0.0f;
    for (int idx = tid; idx < 3 * WI;     idx += THREADS) ((float*)sPrev)[idx] = 0.0f;
    if (tid < WARPS) sProg[tid] = 0;
    __syncthreads();
    // peer shared buffers must be zeroed before any DSMEM push
    asm volatile("barrier.cluster.arrive.aligned;" ::: "memory");
    asm volatile("barrier.cluster.wait.aligned;"   ::: "memory");

    const int ch   = blockIdx.x / NBLK;
    const int blk  = blockIdx.x % NBLK;    // == cluster rank
    const int w    = tid >> 5;
    const int lane = tid & 31;
    const unsigned nextRank = (unsigned)((blk + 1) % NBLK);

    const float* xch = x + ch * HI * WI;

    const unsigned sprogAddr = (unsigned)__cvta_generic_to_shared(&sProg[0]);
    const unsigned sprogOwn  = sprogAddr + w * 4;
    const unsigned pflagAddr = (unsigned)__cvta_generic_to_shared(&sPrevFlag);
    const unsigned pollAddr  = (w == 0) ? pflagAddr : (sprogAddr + (w - 1) * 4);

    // remote push addresses (valid for producer warps w>=5)
    unsigned remRing = 0, remFlag = 0;
    if (w >= 5) {
        unsigned localSlot = (unsigned)__cvta_generic_to_shared(&sPrev[w - 5][0]);
        remRing = mapaClu(localSlot, nextRank);
        if (w == 7) remFlag = mapaClu(pflagAddr, nextRank);
    }

    float* featw = sFeat[w];
    float* h1w   = sH1[w];
    float* h2w   = sH2[w];

    const int m0 = lane, m1 = lane + 32, m2 = lane + 64;
    const float bb0 = sB1[m0], bb1 = sB1[m1], bb2 = sB1[m2];
    const float b2l = (lane < 24) ? sB2[lane] : 0.0f;
    const float b3l = (lane < 12) ? sB3[lane] : 0.0f;
    const float w4l = (lane < 12) ? sW4[lane] : 0.0f;
    const float b4v = sB4v;

    // ---- layer-1 weights in registers: 72 packed f32x2 per lane ----
    ull w1r[72];
    #pragma unroll
    for (int k4 = 0; k4 < 12; ++k4) {
        #pragma unroll
        for (int mi = 0; mi < 3; ++mi) {
            int m = lane + 32 * mi;
            int k = 4 * k4;
            w1r[k4 * 6 + mi * 2 + 0] = packf2(__ldg(W1 + (k + 0) * 96 + m), __ldg(W1 + (k + 1) * 96 + m));
            w1r[k4 * 6 + mi * 2 + 1] = packf2(__ldg(W1 + (k + 2) * 96 + m), __ldg(W1 + (k + 3) * 96 + m));
        }
    }

    // ---- static tap descriptors ----
    // feats 0..23: image taps (lanes 0..23)
    // feats 24..31: delta taps s=lane-24 -> dy=s/7 (0 or 1), dx=s%7  (rows i-3, i-2)
    // feats 32..44: delta taps s=lane+8 (lanes 0..12) -> dy in {1,2}  (rows i-2, i-1)
    // feats 45..47: last3 own deltas -> kept in registers on ALL lanes
    int p1_dy = 0, p1_dx = 0;
    if (lane >= 24) { int s = lane - 24; p1_dy = (s == 7) ? 1 : 0; p1_dx = (s == 7) ? 0 : s; }
    int p2_dy = 0, p2_dx = 0;
    if (lane < 13) { int s = lane + 8; p2_dy = s / 7; p2_dx = s % 7; }

    double sumsqd = 0.0;

    for (int i = 8 * blk + w; i < NI; i += NBLK * WARPS) {
        const float* imgP = nullptr;
        if (lane < 21)      imgP = xch + (i + lane / 7) * WI + (lane % 7);
        else if (lane < 24) imgP = xch + (i + 3) * WI + (lane - 21);

        // tap row local index: l = w-3+dy ; l>=0 -> own sRing[l], else peer slot sPrev[3+l]
        const float* base1 = nullptr;
        if (lane >= 24) {
            int l = w - 3 + p1_dy;
            base1 = (l >= 0) ? &sRing[l][p1_dx] : &sPrev[3 + l][p1_dx];
        }
        const float* base2 = nullptr;
        if (lane < 13) {
            int l = w - 3 + p2_dy;
            base2 = (l >= 0) ? &sRing[l][p2_dx] : &sPrev[3 + l][p2_dx];
        }

        const int    flagBase = (i - 1) * 256;   // i==0 -> negative -> auto-pass
        const int    rowTag   = i * 256;
        const float* tgtRow   = xch + (i + 3) * WI + 3;

        int   fc = 0;
        float d0 = 0.0f, d1 = 0.0f, d2 = 0.0f;   // deltas j-3, j-2, j-1 (all lanes)
        float rowsum = 0.0f;

        for (int j = 0; j < NI; ++j) {
            // ---- single-predecessor wavefront wait ----
            int nd = j + 4; if (nd > NI) nd = NI;
            int need = flagBase + nd;
            if (w == 0) { while (fc < need) fc = ldAcqClu(pollAddr); }
            else        { while (fc < need) fc = ldAcqS(pollAddr); }

            // ---- gather features ----
            float v1;
            if (lane < 24) v1 = __ldg(imgP + j);
            else           v1 = base1[j];
            featw[lane] = v1;
            if (lane < 13) featw[lane + 32] = base2[j];
            __syncwarp();
            float tgt = __ldg(tgtRow + j);       // broadcast load, all lanes
            float f44 = featw[44];

            // ---- layer 1: 48 -> 96 (chunks 0..10 from shared, chunk 11 from regs) ----
            ull a00 = 0, a01 = 0, a10 = 0, a11 = 0, a20 = 0, a21 = 0;
            {
                const ulonglong2* F2 = (const ulonglong2*)featw;
                #pragma unroll
                for (int k4 = 0; k4 < 11; ++k4) {
                    ulonglong2 f = F2[k4];
                    fma2(a00, f.x, w1r[k4 * 6 + 0]); fma2(a01, f.y, w1r[k4 * 6 + 1]);
                    fma2(a10, f.x, w1r[k4 * 6 + 2]); fma2(a11, f.y, w1r[k4 * 6 + 3]);
                    fma2(a20, f.x, w1r[k4 * 6 + 4]); fma2(a21, f.y, w1r[k4 * 6 + 5]);
                }
                ull fa = packf2(f44, d0);
                ull fb = packf2(d1, d2);
                fma2(a00, fa, w1r[66]); fma2(a01, fb, w1r[67]);
                fma2(a10, fa, w1r[68]); fma2(a11, fb, w1r[69]);
                fma2(a20, fa, w1r[70]); fma2(a21, fb, w1r[71]);
            }
            h1w[m0] = ftanh(bb0 + hsum2(a00) + hsum2(a01));
            h1w[m1] = ftanh(bb1 + hsum2(a10) + hsum2(a11));
            h1w[m2] = ftanh(bb2 + hsum2(a20) + hsum2(a21));
            __syncwarp();

            // ---- layer 2: 96 -> 24 (lanes 0..23) ----
            if (lane < 24) {
                ull a0 = 0, a1 = 0, a2 = 0, a3 = 0;
                const ulonglong2* H2v = (const ulonglong2*)h1w;
                #pragma unroll
                for (int k4 = 0; k4 < 24; k4 += 2) {
                    ulonglong2 h  = H2v[k4];
                    ulonglong2 wv = sW2q[k4 * 24 + lane];
                    fma2(a0, h.x, wv.x); fma2(a1, h.y, wv.y);
                    ulonglong2 h2  = H2v[k4 + 1];
                    ulonglong2 wv2 = sW2q[(k4 + 1) * 24 + lane];
                    fma2(a2, h2.x, wv2.x); fma2(a3, h2.y, wv2.y);
                }
                float v = b2l + (hsum2(a0) + hsum2(a1)) + (hsum2(a2) + hsum2(a3));
                h2w[lane] = ftanh(v);
            }
            __syncwarp();

            // ---- layer 3: 24 -> 12 (lanes 0..11) + layer 4 dot-12 ----
            float pr = 0.0f;
            if (lane < 12) {
                ull a0 = 0, a1 = 0;
                const ulonglong2* H3v = (const ulonglong2*)h2w;
                #pragma unroll
                for (int k4 = 0; k4 < 6; ++k4) {
                    ulonglong2 h  = H3v[k4];
                    ulonglong2 wv = sW3q[k4 * 12 + lane];
                    fma2(a0, h.x, wv.x); fma2(a1, h.y, wv.y);
                }
                pr = ftanh(b3l + hsum2(a0) + hsum2(a1)) * w4l;
            }
            // all 32 lanes get the sum (lanes >=12 contribute 0)
            pr += __shfl_xor_sync(0xffffffffu, pr, 16);
            pr += __shfl_xor_sync(0xffffffffu, pr, 8);
            pr += __shfl_xor_sync(0xffffffffu, pr, 4);
            pr += __shfl_xor_sync(0xffffffffu, pr, 2);
            pr += __shfl_xor_sync(0xffffffffu, pr, 1);

            float out_v = ftanh(pr + b4v);
            float delta = tgt - out_v;            // computed by every lane
            d0 = d1; d1 = d2; d2 = delta;

            if (lane == 0) {
                rowsum = fmaf(delta, delta, rowsum);
                sRing[w][3 + j] = delta;                       // own-row ring
                if (w >= 5) stRemoteF(remRing + (3 + j) * 4, delta);  // push to next CTA
                stRelS(sprogOwn, rowTag + j + 1);              // local release flag
                if (w == 7) stRelClu(remFlag, rowTag + j + 1); // cluster release flag
            }
            __syncwarp();
        }
        if (lane == 0) sumsqd += (double)rowsum;
    }
    if (lane == 0) atomicAdd(&g_sumsq, sumsqd);

    // keep all cluster CTAs alive until every peer's pushes have landed
    asm volatile("barrier.cluster.arrive.aligned;" ::: "memory");
    asm volatile("barrier.cluster.wait.aligned;"   ::: "memory");

    // ---- fused finish: last CTA writes the output ----
    __syncthreads();
    if (tid == 0) {
        __threadfence();
        unsigned prev = atomicAdd(&g_done, 1u);
        if (prev == (unsigned)(CH * NBLK - 1)) {
            __threadfence();
            double s = *((volatile double*)&g_sumsq);
            out[0] = (float)sqrt(s / 875520.0);   // b*c*(h-2)*w = 8*3*190*192
        }
    }
}

extern "C" void kernel_launch(void* const* d_in, const int* in_sizes, int n_in,
                              void* d_out, int out_size) {
    const float* x  = (const float*)d_in[0];
    const float* W1 = (const float*)d_in[1];
    const float* b1 = (const float*)d_in[2];
    const float* W2 = (const float*)d_in[3];
    const float* b2 = (const float*)d_in[4];
    const float* W3 = (const float*)d_in[5];
    const float* b3 = (const float*)d_in[6];
    const float* W4 = (const float*)d_in[7];
    const float* b4 = (const float*)d_in[8];

    zero_kernel<<<1, 1>>>();
    codec_kernel<<<CH * NBLK, THREADS>>>(x, W1, b1, W2, b2, W3, b3, W4, b4, (float*)d_out);
}

// round 7
// speedup vs baseline: 1.1292x; 1.1292x over previous
#include <cuda_runtime.h>
#include <math.h>

#define CH 24          // b*c independent planes
#define HI 192
#define WI 192
#define NI 186         // interior rows/cols
#define RINGROWS 64
#define NBLK 6         // CTAs per plane
#define WARPS 16
#define THREADS (WARPS*32)

typedef unsigned long long ull;

__device__ float  g_ring[CH * RINGROWS * WI];   // zero-padded delta rows (only w>=13 rows written)
__device__ int    g_prog[CH * WI];              // per-row completed-column counters
__device__ double g_sumsq;
__device__ unsigned g_done;

__device__ __forceinline__ int ldAcqG(const int* p) {
    int v;
    asm volatile("ld.acquire.gpu.global.b32 %0, [%1];" : "=r"(v) : "l"(p) : "memory");
    return v;
}
__device__ __forceinline__ void stRelG(int* p, int v) {
    asm volatile("st.release.gpu.global.b32 [%0], %1;" :: "l"(p), "r"(v) : "memory");
}
__device__ __forceinline__ int ldAcqS(unsigned a) {
    int v;
    asm volatile("ld.acquire.cta.shared.b32 %0, [%1];" : "=r"(v) : "r"(a) : "memory");
    return v;
}
__device__ __forceinline__ void stRelS(unsigned a, int v) {
    asm volatile("st.release.cta.shared.b32 [%0], %1;" :: "r"(a), "r"(v) : "memory");
}
__device__ __forceinline__ void fma2(ull& d, ull a, ull b) {
    asm("fma.rn.f32x2 %0, %1, %2, %0;" : "+l"(d) : "l"(a), "l"(b));
}
__device__ __forceinline__ float hsum2(ull v) {
    float lo, hi;
    asm("mov.b64 {%0, %1}, %2;" : "=f"(lo), "=f"(hi) : "l"(v));
    return lo + hi;
}
__device__ __forceinline__ ull packf2(float lo, float hi) {
    ull r;
    asm("mov.b64 %0, {%1, %2};" : "=l"(r) : "f"(lo), "f"(hi));
    return r;
}
// tanh(x) = 1 - 2/(e^{2x}+1), via ex2.approx + rcp.approx; abs err ~1e-6
__device__ __forceinline__ float ftanh(float x) {
    float e = __expf(2.0f * x);
    float r;
    asm("rcp.approx.f32 %0, %1;" : "=f"(r) : "f"(e + 1.0f));
    return fmaf(-2.0f, r, 1.0f);
}

__global__ void zero_kernel() {
    int idx = blockIdx.x * blockDim.x + threadIdx.x;
    int stride = gridDim.x * blockDim.x;
    const int n = CH * RINGROWS * WI;
    for (int i = idx; i < n; i += stride) g_ring[i] = 0.0f;
    for (int i = idx; i < CH * WI; i += stride) g_prog[i] = 0;
    if (idx == 0) { g_sumsq = 0.0; g_done = 0; }
}

__global__ __launch_bounds__(THREADS, 1)
void codec_kernel(const float* __restrict__ x,
                  const float* __restrict__ W1, const float* __restrict__ B1,
                  const float* __restrict__ W2, const float* __restrict__ B2,
                  const float* __restrict__ W3, const float* __restrict__ B3,
                  const float* __restrict__ W4, const float* __restrict__ B4,
                  float* __restrict__ out)
{
    // W1: k-major interleaved in shared; W2: k=0..47 in regs, k=48..95 in shared; W3 shared
    __shared__ __align__(16) ulonglong2 sW1q[12 * 96];
    __shared__ __align__(16) ulonglong2 sW2q[12 * 24];
    __shared__ __align__(16) ulonglong2 sW3q[6 * 12];
    __shared__ float sB1[96], sB2[24], sB3[12], sW4[12];
    __shared__ float sB4v;
    __shared__ __align__(16) float sFeat[WARPS][48];
    __shared__ __align__(16) float sH1[WARPS][96];
    __shared__ __align__(16) float sH2[WARPS][24];
    __shared__ __align__(16) float sRing[WARPS][WI];   // per-warp current row deltas
    __shared__ int sProg[WARPS];

    const int tid = threadIdx.x;

    {
        float* f1 = (float*)sW1q;
        for (int idx = tid; idx < 48 * 96; idx += THREADS) {
            int k = idx / 96, m = idx % 96;
            f1[((k >> 2) * 96 + m) * 4 + (k & 3)] = W1[idx];
        }
        float* f2 = (float*)sW2q;
        for (int idx = tid; idx < 48 * 24; idx += THREADS) {
            int k = 48 + idx / 24, m = idx % 24;
            int kk = k - 48;
            f2[((kk >> 2) * 24 + m) * 4 + (kk & 3)] = W2[k * 24 + m];
        }
        float* f3 = (float*)sW3q;
        for (int idx = tid; idx < 24 * 12; idx += THREADS) {
            int k = idx / 12, m = idx % 12;
            f3[((k >> 2) * 12 + m) * 4 + (k & 3)] = W3[idx];
        }
    }
    if (tid < 96) sB1[tid] = B1[tid];
    if (tid < 24) sB2[tid] = B2[tid];
    if (tid < 12) sB3[tid] = B3[tid];
    if (tid < 12) sW4[tid] = W4[tid];
    if (tid == 0) sB4v = B4[0];
    for (int idx = tid; idx < WARPS * WI; idx += THREADS) ((float*)sRing)[idx] = 0.0f;
    if (tid < WARPS) sProg[tid] = 0;
    __syncthreads();

    const int ch   = blockIdx.x / NBLK;
    const int blk  = blockIdx.x % NBLK;
    const int w    = tid >> 5;
    const int lane = tid & 31;

    const float* xch    = x + ch * HI * WI;
    float*       ringCh = g_ring + ch * RINGROWS * WI;
    int*         progCh = g_prog + ch * WI;

    const unsigned sprogAddr = (unsigned)__cvta_generic_to_shared(&sProg[0]);
    const unsigned sprogOwn  = sprogAddr + w * 4;
    const unsigned sprogPrev = sprogAddr + (w - 1) * 4;

    float* featw = sFeat[w];
    float* h1w   = sH1[w];
    float* h2w   = sH2[w];

    const int m0 = lane, m1 = lane + 32, m2 = lane + 64;
    const float bb0 = sB1[m0], bb1 = sB1[m1], bb2 = sB1[m2];
    const float b2l = (lane < 24) ? sB2[lane] : 0.0f;
    const float b3l = (lane < 12) ? sB3[lane] : 0.0f;
    const float w4l = (lane < 12) ? sW4[lane] : 0.0f;
    const float b4v = sB4v;

    // ---- W2 k=0..47 in registers: 24 packed f32x2 per lane (lanes 0..23 use them) ----
    ull w2r[24];
    {
        const int l24 = (lane < 24) ? lane : 0;
        #pragma unroll
        for (int k4 = 0; k4 < 12; ++k4) {
            int k = 4 * k4;
            w2r[k4 * 2 + 0] = packf2(__ldg(W2 + (k + 0) * 24 + l24), __ldg(W2 + (k + 1) * 24 + l24));
            w2r[k4 * 2 + 1] = packf2(__ldg(W2 + (k + 2) * 24 + l24), __ldg(W2 + (k + 3) * 24 + l24));
        }
    }

    // ---- static tap descriptors ----
    // feats 0..23: image taps; 24..31: prev-delta taps s=lane-24; 32..44: s=lane+8 (lane<13);
    // feats 45..47: own last3 deltas, kept in registers on all lanes.
    int p1_dy = 0, p1_dx = 0;
    if (lane >= 24) { int s = lane - 24; p1_dy = (s == 7) ? 1 : 0; p1_dx = (s == 7) ? 0 : s; }
    int p2_dy = 0, p2_dx = 0;
    if (lane < 13) { int s = lane + 8; p2_dy = s / 7; p2_dx = s % 7; }

    double sumsqd = 0.0;

    for (int i = WARPS * blk + w; i < NI; i += NBLK * WARPS) {
        const float* imgP = nullptr;
        if (lane < 21)      imgP = xch + (i + lane / 7) * WI + (lane % 7);
        else if (lane < 24) imgP = xch + (i + 3) * WI + (lane - 21);

        // tap row local index l = w-3+dy: l>=0 -> own-CTA sRing[l]; else global ring
        const float* base1 = nullptr;
        if (lane >= 24) {
            int l = w - 3 + p1_dy;
            base1 = (l >= 0) ? &sRing[l][p1_dx]
                             : ringCh + ((unsigned)(i - 3 + p1_dy) & (RINGROWS - 1)) * WI + p1_dx;
        }
        const float* base2 = nullptr;
        if (lane < 13) {
            int l = w - 3 + p2_dy;
            base2 = (l >= 0) ? &sRing[l][p2_dx]
                             : ringCh + ((unsigned)(i - 3 + p2_dy) & (RINGROWS - 1)) * WI + p2_dx;
        }
        const bool tapG1 = (lane >= 24) && (w - 3 + p1_dy < 0);
        const bool tapG2 = (lane < 13)  && (w - 3 + p2_dy < 0);

        const bool hasShared = (w >= 1);
        const int  sNeedBase = (i - 1) * 256;
        int g0c = NI, g1c = NI, g2c = NI;
        const int *g0p = nullptr, *g1p = nullptr, *g2p = nullptr;
        if (w < 3) {
            int r0 = i - 1 - w; if (r0 >= 0) { g0p = progCh + r0; g0c = 0; }
            if (w < 2) { int r1 = i - 2 - w; if (r1 >= 0) { g1p = progCh + r1; g1c = 0; } }
            if (w < 1) { int r2 = i - 3;     if (r2 >= 0) { g2p = progCh + r2; g2c = 0; } }
        }

        int*         progMe = progCh + i;
        float*       ringW  = ringCh + (i & (RINGROWS - 1)) * WI;
        const float* tgtRow = xch + (i + 3) * WI + 3;
        const bool   pubG   = (w >= WARPS - 3);
        const int    rowTag = i * 256;

        int   spc = 0;
        float d0 = 0.0f, d1 = 0.0f, d2 = 0.0f;   // deltas j-3, j-2, j-1 (all lanes)
        float rowsum = 0.0f;

        for (int j = 0; j < NI; ++j) {
            int nd = j + 4; if (nd > NI) nd = NI;
            // ---- wavefront waits (single shared poll covers all same-CTA rows transitively) ----
            if (hasShared) {
                int sneed = sNeedBase + nd;
                while (spc < sneed) {
                    if (sneed - spc > 300) __nanosleep(256);   // predecessor still on an earlier row
                    spc = ldAcqS(sprogPrev);
                }
            }
            while (g0c < nd) g0c = ldAcqG(g0p);
            while (g1c < nd) g1c = ldAcqG(g1p);
            while (g2c < nd) g2c = ldAcqG(g2p);

            // ---- gather features ----
            float v1;
            if (lane < 24)  v1 = __ldg(imgP + j);
            else if (tapG1) v1 = __ldcg(base1 + j);
            else            v1 = base1[j];
            featw[lane] = v1;
            if (lane < 13) featw[lane + 32] = tapG2 ? __ldcg(base2 + j) : base2[j];
            __syncwarp();
            float tgt = __ldg(tgtRow + j);
            float f44 = featw[44];

            // ---- layer 1: 48 -> 96 (chunks 0..10 from shared feats, chunk 11 from regs) ----
            ull a00 = 0, a01 = 0, a10 = 0, a11 = 0, a20 = 0, a21 = 0;
            {
                const ulonglong2* F2 = (const ulonglong2*)featw;
                #pragma unroll
                for (int k4 = 0; k4 < 11; ++k4) {
                    ulonglong2 f  = F2[k4];
                    ulonglong2 wa = sW1q[k4 * 96 + m0];
                    ulonglong2 wb = sW1q[k4 * 96 + m1];
                    ulonglong2 wc = sW1q[k4 * 96 + m2];
                    fma2(a00, f.x, wa.x); fma2(a01, f.y, wa.y);
                    fma2(a10, f.x, wb.x); fma2(a11, f.y, wb.y);
                    fma2(a20, f.x, wc.x); fma2(a21, f.y, wc.y);
                }
                ull fa = packf2(f44, d0);
                ull fb = packf2(d1, d2);
                ulonglong2 wa = sW1q[11 * 96 + m0];
                ulonglong2 wb = sW1q[11 * 96 + m1];
                ulonglong2 wc = sW1q[11 * 96 + m2];
                fma2(a00, fa, wa.x); fma2(a01, fb, wa.y);
                fma2(a10, fa, wb.x); fma2(a11, fb, wb.y);
                fma2(a20, fa, wc.x); fma2(a21, fb, wc.y);
            }
            h1w[m0] = ftanh(bb0 + hsum2(a00) + hsum2(a01));
            h1w[m1] = ftanh(bb1 + hsum2(a10) + hsum2(a11));
            h1w[m2] = ftanh(bb2 + hsum2(a20) + hsum2(a21));
            __syncwarp();

            // ---- layer 2: 96 -> 24 (lanes 0..23); k<48 from regs, k>=48 from shared ----
            if (lane < 24) {
                ull a0 = 0, a1 = 0, a2 = 0, a3 = 0;
                const ulonglong2* H2v = (const ulonglong2*)h1w;
                #pragma unroll
                for (int k4 = 0; k4 < 12; k4 += 2) {
                    ulonglong2 h = H2v[k4];
                    fma2(a0, h.x, w2r[k4 * 2 + 0]); fma2(a1, h.y, w2r[k4 * 2 + 1]);
                    ulonglong2 h2 = H2v[k4 + 1];
                    fma2(a2, h2.x, w2r[k4 * 2 + 2]); fma2(a3, h2.y, w2r[k4 * 2 + 3]);
                }
                #pragma unroll
                for (int k4 = 12; k4 < 24; k4 += 2) {
                    ulonglong2 h  = H2v[k4];
                    ulonglong2 wv = sW2q[(k4 - 12) * 24 + lane];
                    fma2(a0, h.x, wv.x); fma2(a1, h.y, wv.y);
                    ulonglong2 h2  = H2v[k4 + 1];
                    ulonglong2 wv2 = sW2q[(k4 - 11) * 24 + lane];
                    fma2(a2, h2.x, wv2.x); fma2(a3, h2.y, wv2.y);
                }
                float v = b2l + (hsum2(a0) + hsum2(a1)) + (hsum2(a2) + hsum2(a3));
                h2w[lane] = ftanh(v);
            }
            __syncwarp();

            // ---- layer 3: 24 -> 12 (lanes 0..11) + layer 4 dot-12 ----
            float pr = 0.0f;
            if (lane < 12) {
                ull a0 = 0, a1 = 0;
                const ulonglong2* H3v = (const ulonglong2*)h2w;
                #pragma unroll
                for (int k4 = 0; k4 < 6; ++k4) {
                    ulonglong2 h  = H3v[k4];
                    ulonglong2 wv = sW3q[k4 * 12 + lane];
                    fma2(a0, h.x, wv.x); fma2(a1, h.y, wv.y);
                }
                pr = ftanh(b3l + hsum2(a0) + hsum2(a1)) * w4l;
            }
            pr += __shfl_xor_sync(0xffffffffu, pr, 16);
            pr += __shfl_xor_sync(0xffffffffu, pr, 8);
            pr += __shfl_xor_sync(0xffffffffu, pr, 4);
            pr += __shfl_xor_sync(0xffffffffu, pr, 2);
            pr += __shfl_xor_sync(0xffffffffu, pr, 1);

            float out_v = ftanh(pr + b4v);
            float delta = tgt - out_v;            // every lane computes delta
            d0 = d1; d1 = d2; d2 = delta;

            if (lane == 0) {
                rowsum = fmaf(delta, delta, rowsum);
                sRing[w][3 + j] = delta;                  // own-row ring (shared)
                stRelS(sprogOwn, rowTag + j + 1);         // local release flag
                if (pubG) {
                    ringW[3 + j] = delta;                 // global ring for next-CTA consumers
                    stRelG(progMe, j + 1);
                }
            }
            __syncwarp();
        }
        if (lane == 0) sumsqd += (double)rowsum;
    }
    if (lane == 0) atomicAdd(&g_sumsq, sumsqd);

    // ---- fused finish: last CTA writes the output ----
    __syncthreads();
    if (tid == 0) {
        __threadfence();
        unsigned prev = atomicAdd(&g_done, 1u);
        if (prev == (unsigned)(CH * NBLK - 1)) {
            __threadfence();
            double s = *((volatile double*)&g_sumsq);
            out[0] = (float)sqrt(s / 875520.0);   // b*c*(h-2)*w = 8*3*190*192
        }
    }
}

extern "C" void kernel_launch(void* const* d_in, const int* in_sizes, int n_in,
                              void* d_out, int out_size) {
    const float* x  = (const float*)d_in[0];
    const float* W1 = (const float*)d_in[1];
    const float* b1 = (const float*)d_in[2];
    const float* W2 = (const float*)d_in[3];
    const float* b2 = (const float*)d_in[4];
    const float* W3 = (const float*)d_in[5];
    const float* b3 = (const float*)d_in[6];
    const float* W4 = (const float*)d_in[7];
    const float* b4 = (const float*)d_in[8];

    zero_kernel<<<512, 256>>>();
    codec_kernel<<<CH * NBLK, THREADS>>>(x, W1, b1, W2, b2, W3, b3, W4, b4, (float*)d_out);
}

// round 8
// speedup vs baseline: 1.5686x; 1.3891x over previous
#include <cuda_runtime.h>
#include <math.h>

#define CH 24          // b*c independent planes
#define HI 192
#define WI 192
#define NI 186         // interior rows/cols
#define RINGROWS 64
#define NBLK 6         // CTAs per plane
#define WARPS 8
#define THREADS (WARPS*32)

typedef unsigned long long ull;

__device__ float  g_ring[CH * RINGROWS * WI];   // zero-padded delta rows (rows w>=5 published)
__device__ int    g_prog[CH * WI];              // per-row completed-column counters
__device__ double g_sumsq;
__device__ unsigned g_done;

__device__ __forceinline__ int ldAcqG(const int* p) {
    int v;
    asm volatile("ld.acquire.gpu.global.b32 %0, [%1];" : "=r"(v) : "l"(p) : "memory");
    return v;
}
__device__ __forceinline__ void stRelG(int* p, int v) {
    asm volatile("st.release.gpu.global.b32 [%0], %1;" :: "l"(p), "r"(v) : "memory");
}
__device__ __forceinline__ int ldAcqS(unsigned a) {
    int v;
    asm volatile("ld.acquire.cta.shared.b32 %0, [%1];" : "=r"(v) : "r"(a) : "memory");
    return v;
}
__device__ __forceinline__ void stRelS(unsigned a, int v) {
    asm volatile("st.release.cta.shared.b32 [%0], %1;" :: "r"(a), "r"(v) : "memory");
}
__device__ __forceinline__ void fma2(ull& d, ull a, ull b) {
    asm("fma.rn.f32x2 %0, %1, %2, %0;" : "+l"(d) : "l"(a), "l"(b));
}
__device__ __forceinline__ float hsum2(ull v) {
    float lo, hi;
    asm("mov.b64 {%0, %1}, %2;" : "=f"(lo), "=f"(hi) : "l"(v));
    return lo + hi;
}
__device__ __forceinline__ ull packf2(float lo, float hi) {
    ull r;
    asm("mov.b64 %0, {%1, %2};" : "=l"(r) : "f"(lo), "f"(hi));
    return r;
}
// tanh(x) = 1 - 2/(e^{2x}+1), via ex2.approx + rcp.approx; abs err ~1e-6
__device__ __forceinline__ float ftanh(float x) {
    float e = __expf(2.0f * x);
    float r;
    asm("rcp.approx.f32 %0, %1;" : "=f"(r) : "f"(e + 1.0f));
    return fmaf(-2.0f, r, 1.0f);
}

__global__ void zero_kernel() {
    int idx = blockIdx.x * blockDim.x + threadIdx.x;
    int stride = gridDim.x * blockDim.x;
    const int n = CH * RINGROWS * WI;
    for (int i = idx; i < n; i += stride) g_ring[i] = 0.0f;
    for (int i = idx; i < CH * WI; i += stride) g_prog[i] = 0;
    if (idx == 0) { g_sumsq = 0.0; g_done = 0; }
}

__global__ __launch_bounds__(THREADS, 1)
void codec_kernel(const float* __restrict__ x,
                  const float* __restrict__ W1, const float* __restrict__ B1,
                  const float* __restrict__ W2, const float* __restrict__ B2,
                  const float* __restrict__ W3, const float* __restrict__ B3,
                  const float* __restrict__ W4, const float* __restrict__ B4,
                  float* __restrict__ out)
{
    // W1 rows 0..37 (early feats) k-major interleaved in shared (rows 38,39 zero-pad);
    // W1 rows 38..47 (late feats) in regs; W2 fully in regs; W3 in shared.
    __shared__ __align__(16) ulonglong2 sW1q[10 * 96];
    __shared__ __align__(16) ulonglong2 sW3q[6 * 12];
    __shared__ float sB1[96], sB2[24], sB3[12], sW4[12];
    __shared__ float sB4v;
    __shared__ __align__(16) float sFeatE[WARPS][40];  // early feats 0..37 (+2 pad)
    __shared__ __align__(16) float sH1[WARPS][96];
    __shared__ __align__(16) float sH2[WARPS][24];
    __shared__ __align__(16) float sRing[WARPS][WI];   // per-warp current row deltas
    __shared__ int sProg[WARPS];

    const int tid = threadIdx.x;

    {
        float* f1 = (float*)sW1q;
        for (int idx = tid; idx < 40 * 96; idx += THREADS) {
            int k = idx / 96, m = idx % 96;
            f1[((k >> 2) * 96 + m) * 4 + (k & 3)] = (k < 38) ? W1[k * 96 + m] : 0.0f;
        }
        float* f3 = (float*)sW3q;
        for (int idx = tid; idx < 24 * 12; idx += THREADS) {
            int k = idx / 12, m = idx % 12;
            f3[((k >> 2) * 12 + m) * 4 + (k & 3)] = W3[idx];
        }
    }
    if (tid < 96) sB1[tid] = B1[tid];
    if (tid < 24) sB2[tid] = B2[tid];
    if (tid < 12) sB3[tid] = B3[tid];
    if (tid < 12) sW4[tid] = W4[tid];
    if (tid == 0) sB4v = B4[0];
    for (int idx = tid; idx < WARPS * WI; idx += THREADS) ((float*)sRing)[idx] = 0.0f;
    for (int idx = tid; idx < WARPS * 40; idx += THREADS) ((float*)sFeatE)[idx] = 0.0f;
    if (tid < WARPS) sProg[tid] = 0;
    __syncthreads();

    const int ch   = blockIdx.x / NBLK;
    const int blk  = blockIdx.x % NBLK;
    const int w    = tid >> 5;
    const int lane = tid & 31;

    const float* xch    = x + ch * HI * WI;
    float*       ringCh = g_ring + ch * RINGROWS * WI;
    int*         progCh = g_prog + ch * WI;

    const unsigned sprogAddr = (unsigned)__cvta_generic_to_shared(&sProg[0]);
    const unsigned sprogOwn  = sprogAddr + w * 4;
    const unsigned sprogPrev = sprogAddr + (w - 1) * 4;

    float* featE = sFeatE[w];
    float* h1w   = sH1[w];
    float* h2w   = sH2[w];

    const int m0 = lane, m1 = lane + 32, m2 = lane + 64;
    const float bb0 = sB1[m0], bb1 = sB1[m1], bb2 = sB1[m2];
    const float b2l = (lane < 24) ? sB2[lane] : 0.0f;
    const float b3l = (lane < 12) ? sB3[lane] : 0.0f;
    const float w4l = (lane < 12) ? sW4[lane] : 0.0f;
    const float b4v = sB4v;

    // ---- late W1 (feature rows 38..47): 15 packed f32x2 per lane ----
    ull w1L[15];
    #pragma unroll
    for (int p = 0; p < 5; ++p) {
        #pragma unroll
        for (int mi = 0; mi < 3; ++mi) {
            int m = lane + 32 * mi;
            w1L[p * 3 + mi] = packf2(__ldg(W1 + (38 + 2 * p) * 96 + m),
                                     __ldg(W1 + (39 + 2 * p) * 96 + m));
        }
    }
    // ---- W2 fully in regs: 48 packed f32x2 per lane (lanes 0..23 meaningful) ----
    ull w2r[48];
    {
        const int l24 = (lane < 24) ? lane : 0;
        #pragma unroll
        for (int k4 = 0; k4 < 24; ++k4) {
            int k = 4 * k4;
            w2r[k4 * 2 + 0] = packf2(__ldg(W2 + (k + 0) * 24 + l24), __ldg(W2 + (k + 1) * 24 + l24));
            w2r[k4 * 2 + 1] = packf2(__ldg(W2 + (k + 2) * 24 + l24), __ldg(W2 + (k + 3) * 24 + l24));
        }
    }

    double sumsqd = 0.0;

    for (int i = WARPS * blk + w; i < NI; i += NBLK * WARPS) {
        // early-tap base pointers (feats 0..37)
        // lanes 0..20: img taps dy=lane/7,dx=lane%7 ; 21..23: img row r dx=lane-21
        // lanes 24..30: row i-3 dx=lane-24 ; lane 31: row i-2 dx=0 ; 2nd pass lanes 0..5: row i-2 dx=lane+1
        const float* ring3 = (w >= 3) ? &sRing[w - 3][0]
                                      : ringCh + ((unsigned)(i - 3) & (RINGROWS - 1)) * WI;
        const float* ring2 = (w >= 2) ? &sRing[w - 2][0]
                                      : ringCh + ((unsigned)(i - 2) & (RINGROWS - 1)) * WI;
        const float* ring1 = (w >= 1) ? &sRing[w - 1][0]
                                      : ringCh + ((unsigned)(i - 1) & (RINGROWS - 1)) * WI;
        const bool g3 = (w < 3), g2 = (w < 2), g1 = (w < 1);

        const float* eb1;
        bool eb1img = (lane < 24);
        if (lane < 21)      eb1 = xch + (i + lane / 7) * WI + (lane % 7);
        else if (lane < 24) eb1 = xch + (i + 3) * WI + (lane - 21);
        else if (lane < 31) eb1 = ring3 + (lane - 24);
        else                eb1 = ring2;
        const bool eb1g = (!eb1img) && ((lane < 31) ? g3 : g2);
        const float* eb2 = ring2 + lane + 1;   // lanes 0..5

        // global poll pointers (w==0 only)
        int c1 = NI + 8, c2 = NI + 8, c3 = NI + 8;
        const int *gp1 = nullptr, *gp2 = nullptr, *gp3 = nullptr;
        if (w == 0) {
            if (i - 1 >= 0) { gp1 = progCh + (i - 1); c1 = 0; }
            if (i - 2 >= 0) { gp2 = progCh + (i - 2); c2 = 0; }
            if (i - 3 >= 0) { gp3 = progCh + (i - 3); c3 = 0; }
        }
        const int  sNeedBase = (i - 1) * 256;
        const int  rowTag    = i * 256;
        int*       progMe    = progCh + i;
        float*     ringW     = ringCh + ((unsigned)i & (RINGROWS - 1)) * WI;
        const float* tgtRow  = xch + (i + 3) * WI + 3;
        const bool pubG      = (w >= WARPS - 3);

        int   spc = 0;
        float d0 = 0.0f, d1 = 0.0f, d2 = 0.0f;
        float rowsum = 0.0f;
        ull e00 = 0, e01 = 0, e10 = 0, e11 = 0, e20 = 0, e21 = 0;   // early L1 accumulators

        for (int j = 0; j < NI; ++j) {
            int nd  = j + 4; if (nd  > NI) nd  = NI;
            int nd5 = j + 5; if (nd5 > NI) nd5 = NI;
            // ---- wavefront wait: single shared poll (w>=1, transitive) or global polls (w==0) ----
            if (w) {
                int sneed = sNeedBase + nd;
                while (spc < sneed) spc = ldAcqS(sprogPrev);
            } else {
                while (c1 < nd)  c1 = ldAcqG(gp1);
                while (c2 < nd5) c2 = ldAcqG(gp2);
                while (c3 < nd5) c3 = ldAcqG(gp3);
            }

            // ---- first iteration: build early accumulators in place ----
            if (j == 0) {
                float v = eb1g ? __ldcg(eb1) : (eb1img ? __ldg(eb1) : eb1[0]);
                featE[lane] = v;
                if (lane < 6) featE[32 + lane] = g2 ? __ldcg(eb2) : eb2[0];
                __syncwarp();
                const ulonglong2* F2 = (const ulonglong2*)featE;
                #pragma unroll
                for (int k4 = 0; k4 < 10; ++k4) {
                    ulonglong2 f  = F2[k4];
                    ulonglong2 wa = sW1q[k4 * 96 + m0];
                    ulonglong2 wb = sW1q[k4 * 96 + m1];
                    ulonglong2 wc = sW1q[k4 * 96 + m2];
                    fma2(e00, f.x, wa.x); fma2(e01, f.y, wa.y);
                    fma2(e10, f.x, wb.x); fma2(e11, f.y, wb.y);
                    fma2(e20, f.x, wc.x); fma2(e21, f.y, wc.y);
                }
            }

            // ---- late features: 7 taps of row i-1 (broadcast) + own last-3 deltas (regs) ----
            float f0, f1v, f2v, f3v, f4v, f5v, f6v;
            if (g1) {
                f0  = __ldcg(ring1 + j);     f1v = __ldcg(ring1 + j + 1);
                f2v = __ldcg(ring1 + j + 2); f3v = __ldcg(ring1 + j + 3);
                f4v = __ldcg(ring1 + j + 4); f5v = __ldcg(ring1 + j + 5);
                f6v = __ldcg(ring1 + j + 6);
            } else {
                f0  = ring1[j];     f1v = ring1[j + 1];
                f2v = ring1[j + 2]; f3v = ring1[j + 3];
                f4v = ring1[j + 4]; f5v = ring1[j + 5];
                f6v = ring1[j + 6];
            }
            float tgt = __ldg(tgtRow + j);

            // ---- finish layer 1: add late contributions (15 FFMA2, reg weights) ----
            ull va = packf2(f0, f1v), vb = packf2(f2v, f3v), vc = packf2(f4v, f5v);
            ull vd = packf2(f6v, d0), ve = packf2(d1, d2);
            fma2(e00, va, w1L[0]);  fma2(e10, va, w1L[1]);  fma2(e20, va, w1L[2]);
            fma2(e01, vb, w1L[3]);  fma2(e11, vb, w1L[4]);  fma2(e21, vb, w1L[5]);
            fma2(e00, vc, w1L[6]);  fma2(e10, vc, w1L[7]);  fma2(e20, vc, w1L[8]);
            fma2(e01, vd, w1L[9]);  fma2(e11, vd, w1L[10]); fma2(e21, vd, w1L[11]);
            fma2(e00, ve, w1L[12]); fma2(e10, ve, w1L[13]); fma2(e20, ve, w1L[14]);
            h1w[m0] = ftanh(bb0 + hsum2(e00) + hsum2(e01));
            h1w[m1] = ftanh(bb1 + hsum2(e10) + hsum2(e11));
            h1w[m2] = ftanh(bb2 + hsum2(e20) + hsum2(e21));
            __syncwarp();

            // ---- layer 2: 96 -> 24 (lanes 0..23), weights fully in regs ----
            if (lane < 24) {
                ull a0 = 0, a1 = 0, a2 = 0, a3 = 0;
                const ulonglong2* H = (const ulonglong2*)h1w;
                #pragma unroll
                for (int k4 = 0; k4 < 24; k4 += 2) {
                    ulonglong2 h  = H[k4];
                    fma2(a0, h.x, w2r[2 * k4]);     fma2(a1, h.y, w2r[2 * k4 + 1]);
                    ulonglong2 h2 = H[k4 + 1];
                    fma2(a2, h2.x, w2r[2 * k4 + 2]); fma2(a3, h2.y, w2r[2 * k4 + 3]);
                }
                float v = b2l + (hsum2(a0) + hsum2(a1)) + (hsum2(a2) + hsum2(a3));
                h2w[lane] = ftanh(v);
            }
            __syncwarp();

            // ---- layer 3: 24 -> 12 (lanes 0..11) + layer 4 dot-12 ----
            float pr = 0.0f;
            if (lane < 12) {
                ull a0 = 0, a1 = 0;
                const ulonglong2* H3 = (const ulonglong2*)h2w;
                #pragma unroll
                for (int k4 = 0; k4 < 6; ++k4) {
                    ulonglong2 h  = H3[k4];
                    ulonglong2 wv = sW3q[k4 * 12 + lane];
                    fma2(a0, h.x, wv.x); fma2(a1, h.y, wv.y);
                }
                pr = ftanh(b3l + hsum2(a0) + hsum2(a1)) * w4l;
            }
            pr += __shfl_xor_sync(0xffffffffu, pr, 16);
            pr += __shfl_xor_sync(0xffffffffu, pr, 8);
            pr += __shfl_xor_sync(0xffffffffu, pr, 4);
            pr += __shfl_xor_sync(0xffffffffu, pr, 2);
            pr += __shfl_xor_sync(0xffffffffu, pr, 1);

            float out_v = ftanh(pr + b4v);
            float delta = tgt - out_v;            // every lane
            d0 = d1; d1 = d2; d2 = delta;

            if (lane == 0) {
                rowsum = fmaf(delta, delta, rowsum);
                sRing[w][3 + j] = delta;                  // own-row ring (shared)
                stRelS(sprogOwn, rowTag + j + 1);         // local release flag
                if (pubG) {
                    ringW[3 + j] = delta;                 // global ring for next-CTA consumers
                    stRelG(progMe, j + 1);
                }
            }
            __syncwarp();

            // ---- off-chain: prefetch early feats for pixel j+1 and start its layer 1 ----
            if (j + 1 < NI) {
                int jj = j + 1;
                float v = eb1g ? __ldcg(eb1 + jj) : (eb1img ? __ldg(eb1 + jj) : eb1[jj]);
                featE[lane] = v;
                if (lane < 6) featE[32 + lane] = g2 ? __ldcg(eb2 + jj) : eb2[jj];
                __syncwarp();
                e00 = 0; e01 = 0; e10 = 0; e11 = 0; e20 = 0; e21 = 0;
                const ulonglong2* F2 = (const ulonglong2*)featE;
                #pragma unroll
                for (int k4 = 0; k4 < 10; ++k4) {
                    ulonglong2 f  = F2[k4];
                    ulonglong2 wa = sW1q[k4 * 96 + m0];
                    ulonglong2 wb = sW1q[k4 * 96 + m1];
                    ulonglong2 wc = sW1q[k4 * 96 + m2];
                    fma2(e00, f.x, wa.x); fma2(e01, f.y, wa.y);
                    fma2(e10, f.x, wb.x); fma2(e11, f.y, wb.y);
                    fma2(e20, f.x, wc.x); fma2(e21, f.y, wc.y);
                }
            }
        }
        if (lane == 0) sumsqd += (double)rowsum;
    }
    if (lane == 0) atomicAdd(&g_sumsq, sumsqd);

    // ---- fused finish: last CTA writes the output ----
    __syncthreads();
    if (tid == 0) {
        __threadfence();
        unsigned prev = atomicAdd(&g_done, 1u);
        if (prev == (unsigned)(CH * NBLK - 1)) {
            __threadfence();
            double s = *((volatile double*)&g_sumsq);
            out[0] = (float)sqrt(s / 875520.0);   // b*c*(h-2)*w = 8*3*190*192
        }
    }
}

extern "C" void kernel_launch(void* const* d_in, const int* in_sizes, int n_in,
                              void* d_out, int out_size) {
    const float* x  = (const float*)d_in[0];
    const float* W1 = (const float*)d_in[1];
    const float* b1 = (const float*)d_in[2];
    const float* W2 = (const float*)d_in[3];
    const float* b2 = (const float*)d_in[4];
    const float* W3 = (const float*)d_in[5];
    const float* b3 = (const float*)d_in[6];
    const float* W4 = (const float*)d_in[7];
    const float* b4 = (const float*)d_in[8];

    zero_kernel<<<512, 256>>>();
    codec_kernel<<<CH * NBLK, THREADS>>>(x, W1, b1, W2, b2, W3, b3, W4, b4, (float*)d_out);
}